// round 1
// baseline (speedup 1.0000x reference)
#include <cuda_runtime.h>
#include <math.h>

#define NIMG 24               // B*C = 8*3
#define NBATCHC 3             // channels per weight
#define HH 512
#define WW 512
#define PLANE (HH*WW)
#define NITER 10
#define EPSC 2e-4f
#define TAU 0.25f
#define ROWS_PER_BLOCK 2
#define BLOCKS_X (HH/ROWS_PER_BLOCK)   // 256 blocks per image

// ---------------- scratch state (static device globals; no runtime alloc) ----
__device__ float g_pt[2][NIMG][2][PLANE];       // double-buffered dual field
__device__ float g_bsum[NIMG][BLOCKS_X][2];     // per-block partial sums {dt^2, norm}
__device__ float g_Einit[NIMG];
__device__ float g_Eprev[NIMG];
__device__ int   g_done[NIMG];
__device__ int   g_lastbuf[NIMG];

// ---------------- init ------------------------------------------------------
__global__ void tv_init_kernel() {
    int i = threadIdx.x;
    if (i < NIMG) {
        g_done[i]    = 0;
        g_Einit[i]   = 0.f;
        g_Eprev[i]   = 0.f;
        g_lastbuf[i] = 0;
    }
}

// ---------------- main iteration kernel ------------------------------------
// One thread per pixel. Block = (512, 2) covering 2 rows; grid = (256, NIMG).
// Computes dt (divergence) at center + neighbors (to form forward gradients of
// out=img+dt), updates pt into the write buffer, and produces deterministic
// per-block partial sums of dt^2 and |grad|.
template<bool FIRST>
__global__ void __launch_bounds__(1024)
tv_iter_kernel(const float* __restrict__ img,
               const float* __restrict__ weight,
               int rbuf, int wbuf)
{
    const int b = blockIdx.y;
    if (g_done[b]) return;

    const int r   = blockIdx.x * ROWS_PER_BLOCK + threadIdx.y;
    const int c   = threadIdx.x;
    const int idx = r * WW + c;

    const float* __restrict__ im = img + b * PLANE;
    const float* __restrict__ P0 = &g_pt[rbuf][b][0][0];
    const float* __restrict__ P1 = &g_pt[rbuf][b][1][0];
    float* __restrict__ Q0 = &g_pt[wbuf][b][0][0];
    float* __restrict__ Q1 = &g_pt[wbuf][b][1][0];

    const float wgt = __ldg(&weight[b / NBATCHC]);

    float p0c, p1c, dt_c, out_c, g0, g1;

    if (FIRST) {
        // pt == 0 everywhere: dt = 0, out = img
        p0c = 0.f; p1c = 0.f; dt_c = 0.f;
        out_c = __ldg(&im[idx]);
        g0 = (r < HH - 1) ? (__ldg(&im[idx + WW]) - out_c) : 0.f;
        g1 = (c < WW - 1) ? (__ldg(&im[idx + 1])  - out_c) : 0.f;
    } else {
        p0c = P0[idx];
        p1c = P1[idx];
        float p0u = (r > 0) ? P0[idx - WW] : 0.f;
        float p1l = (c > 0) ? P1[idx - 1]  : 0.f;
        // same op order as reference: (-(p0+p1)) + up + left
        dt_c = -(p0c + p1c); dt_c += p0u; dt_c += p1l;
        out_c = __ldg(&im[idx]) + dt_c;

        if (r < HH - 1) {                       // dt at (r+1, c)
            float p0d  = P0[idx + WW];
            float p1d  = P1[idx + WW];
            float p1dl = (c > 0) ? P1[idx + WW - 1] : 0.f;
            float dt_d = -(p0d + p1d); dt_d += p0c; dt_d += p1dl;
            g0 = (__ldg(&im[idx + WW]) + dt_d) - out_c;
        } else g0 = 0.f;

        if (c < WW - 1) {                       // dt at (r, c+1)
            float p0r  = P0[idx + 1];
            float p1r  = P1[idx + 1];
            float p0ur = (r > 0) ? P0[idx - WW + 1] : 0.f;
            float dt_r = -(p0r + p1r); dt_r += p0ur; dt_r += p1c;
            g1 = (__ldg(&im[idx + 1]) + dt_r) - out_c;
        } else g1 = 0.f;
    }

    float s    = g0 * g0 + g1 * g1;
    float norm = sqrtf(s);                      // sqrtf(0)=0 matches masked ref

    float denom = 1.0f + (TAU / wgt) * norm;
    float rden  = 1.0f / denom;
    Q0[idx] = (p0c - TAU * g0) * rden;
    Q1[idx] = (p1c - TAU * g1) * rden;

    // ---- deterministic block reduction of {dt^2, norm} ----
    float ld = dt_c * dt_c;
    float ln = norm;
    #pragma unroll
    for (int o = 16; o > 0; o >>= 1) {
        ld += __shfl_down_sync(0xffffffffu, ld, o);
        ln += __shfl_down_sync(0xffffffffu, ln, o);
    }
    __shared__ float sd[32], sn[32];
    int tid  = threadIdx.y * blockDim.x + threadIdx.x;   // 0..1023
    int wid  = tid >> 5;
    int lane = tid & 31;
    if (lane == 0) { sd[wid] = ld; sn[wid] = ln; }
    __syncthreads();
    if (tid < 32) {
        ld = sd[tid];
        ln = sn[tid];
        #pragma unroll
        for (int o = 16; o > 0; o >>= 1) {
            ld += __shfl_down_sync(0xffffffffu, ld, o);
            ln += __shfl_down_sync(0xffffffffu, ln, o);
        }
        if (tid == 0) {
            g_bsum[b][blockIdx.x][0] = ld;
            g_bsum[b][blockIdx.x][1] = ln;
        }
    }
}

// ---------------- convergence kernel (one block per image) ------------------
__global__ void tv_conv_kernel(const float* __restrict__ weight, int iter, int wbuf)
{
    const int b = blockIdx.x;
    if (g_done[b]) return;
    const int t = threadIdx.x;                  // 256 threads = BLOCKS_X entries

    float ld = g_bsum[b][t][0];
    float ln = g_bsum[b][t][1];
    #pragma unroll
    for (int o = 16; o > 0; o >>= 1) {
        ld += __shfl_down_sync(0xffffffffu, ld, o);
        ln += __shfl_down_sync(0xffffffffu, ln, o);
    }
    __shared__ float sd[8], sn[8];
    int wid = t >> 5, lane = t & 31;
    if (lane == 0) { sd[wid] = ld; sn[wid] = ln; }
    __syncthreads();
    if (t == 0) {
        for (int i = 1; i < 8; i++) { ld += sd[i]; ln += sn[i]; }
        float wgt = __ldg(&weight[b / NBATCHC]);
        float Et  = (ld + wgt * ln) / (float)PLANE;
        float Einit = g_Einit[b];
        if (iter == 0) { Einit = Et; g_Einit[b] = Et; }
        bool conv = (iter > 0) && (fabsf(g_Eprev[b] - Et) < EPSC * Einit);
        g_Eprev[b]  = Et;
        g_lastbuf[b] = wbuf;
        if (conv) g_done[b] = 1;
    }
}

// ---------------- final output: out = img + div(pt at second-to-last write) -
__global__ void __launch_bounds__(1024)
tv_final_kernel(const float* __restrict__ img, float* __restrict__ out)
{
    const int b   = blockIdx.y;
    const int r   = blockIdx.x * ROWS_PER_BLOCK + threadIdx.y;
    const int c   = threadIdx.x;
    const int idx = r * WW + c;

    const int buf = 1 - g_lastbuf[b];           // pt at entry of last applied iter
    const float* __restrict__ P0 = &g_pt[buf][b][0][0];
    const float* __restrict__ P1 = &g_pt[buf][b][1][0];

    float p0c = P0[idx];
    float p1c = P1[idx];
    float p0u = (r > 0) ? P0[idx - WW] : 0.f;
    float p1l = (c > 0) ? P1[idx - 1]  : 0.f;
    float dt = -(p0c + p1c); dt += p0u; dt += p1l;
    out[b * PLANE + idx] = __ldg(&img[b * PLANE + idx]) + dt;
}

// ---------------- launch ----------------------------------------------------
extern "C" void kernel_launch(void* const* d_in, const int* in_sizes, int n_in,
                              void* d_out, int out_size)
{
    const float* img = (const float*)d_in[0];   // [8,3,512,512] f32
    const float* wgt = (const float*)d_in[1];   // [8] f32
    float* out = (float*)d_out;

    dim3 block(WW, ROWS_PER_BLOCK);             // 512 x 2 = 1024 threads
    dim3 grid(BLOCKS_X, NIMG);                  // 256 x 24

    tv_init_kernel<<<1, 32>>>();

    // iteration 0 (pt == 0): write buffer 0
    tv_iter_kernel<true><<<grid, block>>>(img, wgt, 0, 0);
    tv_conv_kernel<<<NIMG, BLOCKS_X>>>(wgt, 0, 0);

    for (int it = 1; it < NITER; ++it) {
        int wbuf = it & 1;
        int rbuf = 1 - wbuf;
        tv_iter_kernel<false><<<grid, block>>>(img, wgt, rbuf, wbuf);
        tv_conv_kernel<<<NIMG, BLOCKS_X>>>(wgt, it, wbuf);
    }

    tv_final_kernel<<<grid, block>>>(img, out);
}

// round 2
// speedup vs baseline: 1.2398x; 1.2398x over previous
#include <cuda_runtime.h>
#include <math.h>

#define NIMG 24               // B*C = 8*3
#define HH 512
#define WW 512
#define PLANE (HH*WW)
#define NITER 10
#define EPSC 2e-4f
#define TAU 0.25f
#define TBX 128               // threads in x (each handles 4 px)
#define TBY 8                 // rows per block
#define BLOCKS_X (HH/TBY)     // 64 blocks per image

// ---------------- scratch state (static device globals) ---------------------
__device__ float g_pt[2][NIMG][2][PLANE];       // double-buffered dual field
__device__ float g_bsum[NIMG][BLOCKS_X][2];     // per-block partials {dt^2, norm}
__device__ int   g_cnt[NIMG];                   // arrival counters
__device__ float g_Einit[NIMG];
__device__ float g_Eprev[NIMG];
__device__ int   g_done[NIMG];
__device__ int   g_lastbuf[NIMG];

// ---------------- init ------------------------------------------------------
__global__ void tv_init_kernel() {
    int i = threadIdx.x;
    if (i < NIMG) {
        g_done[i]    = 0;
        g_Einit[i]   = 0.f;
        g_Eprev[i]   = 0.f;
        g_lastbuf[i] = 0;
        g_cnt[i]     = 0;
    }
}

// ---------------- main iteration kernel (vectorized, fused reduce) ----------
// Each thread: 4 consecutive pixels (float4). Block (128,8) = 1024 thr = 512x8
// tile. Grid (64, NIMG). Neighbor columns come from in-vector shifts +
// warp shuffles; warp-seam elements fall back to scalar global loads.
// The last-arriving block per image does the cross-block energy reduction
// (fixed order -> deterministic) and updates convergence state.
template<bool FIRST>
__global__ void __launch_bounds__(1024)
tv_iter_kernel(const float* __restrict__ img,
               const float* __restrict__ weight,
               int rbuf, int wbuf, int iter)
{
    const int b = blockIdx.y;
    if (g_done[b]) return;

    const int r    = blockIdx.x * TBY + threadIdx.y;
    const int c4   = threadIdx.x * 4;
    const int idx  = r * WW + c4;
    const int i4   = idx >> 2;
    const int lane = threadIdx.x & 31;
    const bool lastR = (r == HH - 1);
    const bool haveR = (c4 + 4 < WW);

    const float*  __restrict__ imp = img + b * PLANE;
    const float4* __restrict__ im4 = (const float4*)imp;
    const float*  __restrict__ P0s = &g_pt[rbuf][b][0][0];
    const float*  __restrict__ P1s = &g_pt[rbuf][b][1][0];
    const float4* __restrict__ P0  = (const float4*)P0s;
    const float4* __restrict__ P1  = (const float4*)P1s;
    float4* __restrict__ Q0 = (float4*)&g_pt[wbuf][b][0][0];
    float4* __restrict__ Q1 = (float4*)&g_pt[wbuf][b][1][0];

    const float wgt = __ldg(&weight[b / 3]);

    float4 imc = __ldg(&im4[i4]);
    float4 imd = lastR ? make_float4(0,0,0,0) : __ldg(&im4[i4 + WW/4]);

    float4 p0c, p1c, p0u, p0d, p1d;
    float p1l, p1dl, p0r, p1r, p0ur;
    if (FIRST) {
        p0c = p1c = p0u = p0d = p1d = make_float4(0,0,0,0);
        p1l = p1dl = p0r = p1r = p0ur = 0.f;
    } else {
        p0c = P0[i4];
        p1c = P1[i4];
        p0u = (r > 0) ? P0[i4 - WW/4] : make_float4(0,0,0,0);
        if (!lastR) { p0d = P0[i4 + WW/4]; p1d = P1[i4 + WW/4]; }
        else        { p0d = p1d = make_float4(0,0,0,0); }

        p1l  = __shfl_up_sync(0xffffffffu, p1c.w, 1);
        p1dl = __shfl_up_sync(0xffffffffu, p1d.w, 1);
        if (lane == 0) {
            p1l  = (c4 > 0)            ? P1s[idx - 1]      : 0.f;
            p1dl = (c4 > 0 && !lastR)  ? P1s[idx + WW - 1] : 0.f;
        }
        p0r  = __shfl_down_sync(0xffffffffu, p0c.x, 1);
        p1r  = __shfl_down_sync(0xffffffffu, p1c.x, 1);
        p0ur = __shfl_down_sync(0xffffffffu, p0u.x, 1);
        if (lane == 31 && haveR) {
            p0r  = P0s[idx + 4];
            p1r  = P1s[idx + 4];
            p0ur = (r > 0) ? P0s[idx + 4 - WW] : 0.f;
        }
    }
    float imr = __shfl_down_sync(0xffffffffu, imc.x, 1);
    if (lane == 31 && haveR) imr = __ldg(&imp[idx + 4]);

    // divergence dt at the 4 center pixels (same op order as reference)
    float dt0 = -(p0c.x + p1c.x) + p0u.x + p1l;
    float dt1 = -(p0c.y + p1c.y) + p0u.y + p1c.x;
    float dt2 = -(p0c.z + p1c.z) + p0u.z + p1c.y;
    float dt3 = -(p0c.w + p1c.w) + p0u.w + p1c.z;

    float o0 = imc.x + dt0, o1 = imc.y + dt1;
    float o2 = imc.z + dt2, o3 = imc.w + dt3;

    // vertical forward gradient: out(r+1,c) - out(r,c)
    float g00, g01, g02, g03;
    if (!lastR) {
        float dd0 = -(p0d.x + p1d.x) + p0c.x + p1dl;
        float dd1 = -(p0d.y + p1d.y) + p0c.y + p1d.x;
        float dd2 = -(p0d.z + p1d.z) + p0c.z + p1d.y;
        float dd3 = -(p0d.w + p1d.w) + p0c.w + p1d.z;
        g00 = (imd.x + dd0) - o0;
        g01 = (imd.y + dd1) - o1;
        g02 = (imd.z + dd2) - o2;
        g03 = (imd.w + dd3) - o3;
    } else { g00 = g01 = g02 = g03 = 0.f; }

    // horizontal forward gradient
    float dtr = -(p0r + p1r) + p0ur + p1c.w;
    float orr = imr + dtr;
    float g10 = o1 - o0;
    float g11 = o2 - o1;
    float g12 = o3 - o2;
    float g13 = haveR ? (orr - o3) : 0.f;

    // dual update + local energy accumulation
    float ld = 0.f, ln = 0.f;
    float4 q0, q1;
    {
        float s = g00*g00 + g10*g10; float nm = sqrtf(s);
        float rd = 1.0f / (1.0f + (TAU/wgt)*nm);
        q0.x = (p0c.x - TAU*g00)*rd; q1.x = (p1c.x - TAU*g10)*rd;
        ln += nm; ld += dt0*dt0;
    }
    {
        float s = g01*g01 + g11*g11; float nm = sqrtf(s);
        float rd = 1.0f / (1.0f + (TAU/wgt)*nm);
        q0.y = (p0c.y - TAU*g01)*rd; q1.y = (p1c.y - TAU*g11)*rd;
        ln += nm; ld += dt1*dt1;
    }
    {
        float s = g02*g02 + g12*g12; float nm = sqrtf(s);
        float rd = 1.0f / (1.0f + (TAU/wgt)*nm);
        q0.z = (p0c.z - TAU*g02)*rd; q1.z = (p1c.z - TAU*g12)*rd;
        ln += nm; ld += dt2*dt2;
    }
    {
        float s = g03*g03 + g13*g13; float nm = sqrtf(s);
        float rd = 1.0f / (1.0f + (TAU/wgt)*nm);
        q0.w = (p0c.w - TAU*g03)*rd; q1.w = (p1c.w - TAU*g13)*rd;
        ln += nm; ld += dt3*dt3;
    }
    Q0[i4] = q0;
    Q1[i4] = q1;

    // ---- deterministic block reduction of {dt^2, norm} ----
    #pragma unroll
    for (int o = 16; o > 0; o >>= 1) {
        ld += __shfl_down_sync(0xffffffffu, ld, o);
        ln += __shfl_down_sync(0xffffffffu, ln, o);
    }
    __shared__ float sd[32], sn[32];
    __shared__ int s_isLast;
    const int tid = threadIdx.y * TBX + threadIdx.x;
    const int wid = tid >> 5;
    if (lane == 0) { sd[wid] = ld; sn[wid] = ln; }
    __syncthreads();
    if (tid < 32) {
        ld = sd[tid];
        ln = sn[tid];
        #pragma unroll
        for (int o = 16; o > 0; o >>= 1) {
            ld += __shfl_down_sync(0xffffffffu, ld, o);
            ln += __shfl_down_sync(0xffffffffu, ln, o);
        }
        if (tid == 0) {
            g_bsum[b][blockIdx.x][0] = ld;
            g_bsum[b][blockIdx.x][1] = ln;
            __threadfence();
            int old = atomicAdd(&g_cnt[b], 1);
            s_isLast = (old == BLOCKS_X - 1) ? 1 : 0;
        }
    }
    __syncthreads();

    // ---- last-arriving block: cross-block reduce + convergence update ----
    if (s_isLast && tid < 32) {
        float a  = g_bsum[b][tid][0] + g_bsum[b][tid + 32][0];
        float n2 = g_bsum[b][tid][1] + g_bsum[b][tid + 32][1];
        #pragma unroll
        for (int o = 16; o > 0; o >>= 1) {
            a  += __shfl_down_sync(0xffffffffu, a,  o);
            n2 += __shfl_down_sync(0xffffffffu, n2, o);
        }
        if (tid == 0) {
            float Et    = (a + wgt * n2) / (float)PLANE;
            float Einit = (iter == 0) ? Et : g_Einit[b];
            if (iter == 0) g_Einit[b] = Et;
            bool conv = (iter > 0) && (fabsf(g_Eprev[b] - Et) < EPSC * Einit);
            g_Eprev[b]   = Et;
            g_lastbuf[b] = wbuf;
            g_cnt[b]     = 0;
            if (conv) g_done[b] = 1;
        }
    }
}

// ---------------- final output: out = img + div(pt at entry of last iter) ---
__global__ void __launch_bounds__(1024)
tv_final_kernel(const float* __restrict__ img, float* __restrict__ out)
{
    const int b    = blockIdx.y;
    const int r    = blockIdx.x * TBY + threadIdx.y;
    const int c4   = threadIdx.x * 4;
    const int idx  = r * WW + c4;
    const int i4   = idx >> 2;
    const int lane = threadIdx.x & 31;

    const int buf = 1 - g_lastbuf[b];           // pt at entry of last applied iter
    const float*  __restrict__ P0s = &g_pt[buf][b][0][0];
    const float*  __restrict__ P1s = &g_pt[buf][b][1][0];
    const float4* __restrict__ P0  = (const float4*)P0s;
    const float4* __restrict__ P1  = (const float4*)P1s;

    float4 p0c = P0[i4];
    float4 p1c = P1[i4];
    float4 p0u = (r > 0) ? P0[i4 - WW/4] : make_float4(0,0,0,0);
    float p1l = __shfl_up_sync(0xffffffffu, p1c.w, 1);
    if (lane == 0) p1l = (c4 > 0) ? P1s[idx - 1] : 0.f;

    float4 imc = __ldg(&((const float4*)(img + b * PLANE))[i4]);
    float4 o;
    o.x = imc.x + (-(p0c.x + p1c.x) + p0u.x + p1l);
    o.y = imc.y + (-(p0c.y + p1c.y) + p0u.y + p1c.x);
    o.z = imc.z + (-(p0c.z + p1c.z) + p0u.z + p1c.y);
    o.w = imc.w + (-(p0c.w + p1c.w) + p0u.w + p1c.z);
    ((float4*)out)[b * (PLANE/4) + i4] = o;
}

// ---------------- launch ----------------------------------------------------
extern "C" void kernel_launch(void* const* d_in, const int* in_sizes, int n_in,
                              void* d_out, int out_size)
{
    const float* img = (const float*)d_in[0];   // [8,3,512,512] f32
    const float* wgt = (const float*)d_in[1];   // [8] f32
    float* out = (float*)d_out;

    dim3 block(TBX, TBY);                       // 128 x 8 = 1024 threads
    dim3 grid(BLOCKS_X, NIMG);                  // 64 x 24

    tv_init_kernel<<<1, 32>>>();

    // iteration 0 (pt == 0): write buffer 0
    tv_iter_kernel<true><<<grid, block>>>(img, wgt, 0, 0, 0);

    for (int it = 1; it < NITER; ++it) {
        int wbuf = it & 1;
        int rbuf = 1 - wbuf;
        tv_iter_kernel<false><<<grid, block>>>(img, wgt, rbuf, wbuf, it);
    }

    tv_final_kernel<<<grid, block>>>(img, out);
}

// round 3
// speedup vs baseline: 1.8409x; 1.4849x over previous
#include <cuda_runtime.h>
#include <math.h>

#define NIMG 24               // B*C = 8*3
#define HH 512
#define WW 512
#define PLANE (HH*WW)
#define NITER 10
#define EPSC 2e-4f
#define TAU 0.25f
#define TBX 128               // threads per block: one 512-px row strip
#define RPT 8                 // rows per block/thread
#define BLOCKS_X (HH/RPT)     // 64 blocks per image
#define W4 (WW/4)             // 128 float4 per row

// ---------------- scratch state (static device globals) ---------------------
__device__ float g_pt[2][NIMG][2][PLANE];       // double-buffered dual field
__device__ float g_bsum[NIMG][BLOCKS_X][2];     // per-block partials {dt^2, norm}
__device__ int   g_cnt[NIMG];                   // arrival counters
__device__ float g_Einit[NIMG];
__device__ float g_Eprev[NIMG];
__device__ int   g_done[NIMG];
__device__ int   g_lastbuf[NIMG];

__global__ void tv_init_kernel() {
    int i = threadIdx.x;
    if (i < NIMG) {
        g_done[i]    = 0;
        g_Einit[i]   = 0.f;
        g_Eprev[i]   = 0.f;
        g_lastbuf[i] = 0;
        g_cnt[i]     = 0;
    }
}

// ---------------- main iteration kernel --------------------------------------
// Block = 128 threads covering a 512x8 strip (4 px/thread/row, rolling over 8
// rows). Old-pt reads use __ldcs (evict-first: the lines are dead after this
// read and will be fully overwritten next iteration) to keep img + the write
// buffer L2-resident across iterations. Fused deterministic energy reduction;
// last-arriving block per image updates convergence state.
template<bool FIRST>
__global__ void __launch_bounds__(TBX)
tv_iter_kernel(const float* __restrict__ img,
               const float* __restrict__ weight,
               int rbuf, int wbuf, int iter)
{
    const int b = blockIdx.y;
    if (g_done[b]) return;

    const int tx   = threadIdx.x;
    const int lane = tx & 31;
    const int c4   = tx * 4;
    const int r0   = blockIdx.x * RPT;
    const bool haveR = (c4 + 4 < WW);

    const float*  __restrict__ imp = img + b * PLANE;
    const float4* __restrict__ im4 = (const float4*)imp;
    const float*  __restrict__ P0s = &g_pt[rbuf][b][0][0];
    const float*  __restrict__ P1s = &g_pt[rbuf][b][1][0];
    const float4* __restrict__ P0  = (const float4*)P0s;
    const float4* __restrict__ P1  = (const float4*)P1s;
    float4* __restrict__ Q0 = (float4*)&g_pt[wbuf][b][0][0];
    float4* __restrict__ Q1 = (float4*)&g_pt[wbuf][b][1][0];

    const float wgt = __ldg(&weight[b / 3]);
    const float tw  = TAU / wgt;

    const int i40 = r0 * W4 + tx;

    float ld = 0.f, ln = 0.f;

    if (FIRST) {
        // pt == 0: out = img, dt = 0
        float4 im_cur = __ldg(&im4[i40]);
        #pragma unroll
        for (int k = 0; k < RPT; ++k) {
            const int r  = r0 + k;
            const int iv = i40 + k * W4;
            const bool lastrow = (r == HH - 1);
            float4 im_nx = make_float4(0,0,0,0);
            if (!lastrow) im_nx = __ldg(&im4[iv + W4]);

            float4 g0;
            if (!lastrow) {
                g0.x = im_nx.x - im_cur.x; g0.y = im_nx.y - im_cur.y;
                g0.z = im_nx.z - im_cur.z; g0.w = im_nx.w - im_cur.w;
            } else g0 = make_float4(0,0,0,0);

            float imr = __shfl_down_sync(0xffffffffu, im_cur.x, 1);
            if (lane == 31 && haveR) imr = __ldg(&imp[r * WW + c4 + 4]);
            float4 g1;
            g1.x = im_cur.y - im_cur.x;
            g1.y = im_cur.z - im_cur.y;
            g1.z = im_cur.w - im_cur.z;
            g1.w = haveR ? (imr - im_cur.w) : 0.f;

            float4 q0, q1;
            {
                float nm = sqrtf(g0.x*g0.x + g1.x*g1.x);
                float rd = 1.0f / (1.0f + tw * nm);
                q0.x = (-TAU * g0.x) * rd; q1.x = (-TAU * g1.x) * rd; ln += nm;
            }
            {
                float nm = sqrtf(g0.y*g0.y + g1.y*g1.y);
                float rd = 1.0f / (1.0f + tw * nm);
                q0.y = (-TAU * g0.y) * rd; q1.y = (-TAU * g1.y) * rd; ln += nm;
            }
            {
                float nm = sqrtf(g0.z*g0.z + g1.z*g1.z);
                float rd = 1.0f / (1.0f + tw * nm);
                q0.z = (-TAU * g0.z) * rd; q1.z = (-TAU * g1.z) * rd; ln += nm;
            }
            {
                float nm = sqrtf(g0.w*g0.w + g1.w*g1.w);
                float rd = 1.0f / (1.0f + tw * nm);
                q0.w = (-TAU * g0.w) * rd; q1.w = (-TAU * g1.w) * rd; ln += nm;
            }
            Q0[iv] = q0; Q1[iv] = q1;
            im_cur = im_nx;
        }
    } else {
        // rolling prologue: row r0
        float4 p0_cur = __ldcs(&P0[i40]);
        float4 p1_cur = __ldcs(&P1[i40]);
        float4 im_cur = __ldg(&im4[i40]);
        float4 p0u = make_float4(0,0,0,0);
        if (r0 > 0) p0u = __ldcs(&P0[i40 - W4]);
        float p1l = __shfl_up_sync(0xffffffffu, p1_cur.w, 1);
        if (lane == 0) p1l = (c4 > 0) ? __ldcs(&P1s[r0 * WW + c4 - 1]) : 0.f;

        float4 dt_cur;
        dt_cur.x = -(p0_cur.x + p1_cur.x) + p0u.x + p1l;
        dt_cur.y = -(p0_cur.y + p1_cur.y) + p0u.y + p1_cur.x;
        dt_cur.z = -(p0_cur.z + p1_cur.z) + p0u.z + p1_cur.y;
        dt_cur.w = -(p0_cur.w + p1_cur.w) + p0u.w + p1_cur.z;

        #pragma unroll
        for (int k = 0; k < RPT; ++k) {
            const int r  = r0 + k;
            const int iv = i40 + k * W4;
            const bool lastrow = (r == HH - 1);

            float4 p0_nx, p1_nx, im_nx, dt_nx;
            if (!lastrow) {
                p0_nx = __ldcs(&P0[iv + W4]);
                p1_nx = __ldcs(&P1[iv + W4]);
                im_nx = __ldg(&im4[iv + W4]);
                float p1ln = __shfl_up_sync(0xffffffffu, p1_nx.w, 1);
                if (lane == 0)
                    p1ln = (c4 > 0) ? __ldcs(&P1s[(r + 1) * WW + c4 - 1]) : 0.f;
                dt_nx.x = -(p0_nx.x + p1_nx.x) + p0_cur.x + p1ln;
                dt_nx.y = -(p0_nx.y + p1_nx.y) + p0_cur.y + p1_nx.x;
                dt_nx.z = -(p0_nx.z + p1_nx.z) + p0_cur.z + p1_nx.y;
                dt_nx.w = -(p0_nx.w + p1_nx.w) + p0_cur.w + p1_nx.z;
            }

            float4 out_cur;
            out_cur.x = im_cur.x + dt_cur.x;
            out_cur.y = im_cur.y + dt_cur.y;
            out_cur.z = im_cur.z + dt_cur.z;
            out_cur.w = im_cur.w + dt_cur.w;

            float4 g0;
            if (!lastrow) {
                g0.x = (im_nx.x + dt_nx.x) - out_cur.x;
                g0.y = (im_nx.y + dt_nx.y) - out_cur.y;
                g0.z = (im_nx.z + dt_nx.z) - out_cur.z;
                g0.w = (im_nx.w + dt_nx.w) - out_cur.w;
            } else g0 = make_float4(0,0,0,0);

            float orr = __shfl_down_sync(0xffffffffu, out_cur.x, 1);
            if (lane == 31 && haveR) {
                float q0s = __ldcs(&P0s[r * WW + c4 + 4]);
                float q1s = __ldcs(&P1s[r * WW + c4 + 4]);
                float qus = (r > 0) ? __ldcs(&P0s[(r - 1) * WW + c4 + 4]) : 0.f;
                float dtr = -(q0s + q1s) + qus + p1_cur.w;
                orr = __ldg(&imp[r * WW + c4 + 4]) + dtr;
            }
            float4 g1;
            g1.x = out_cur.y - out_cur.x;
            g1.y = out_cur.z - out_cur.y;
            g1.z = out_cur.w - out_cur.z;
            g1.w = haveR ? (orr - out_cur.w) : 0.f;

            float4 q0, q1;
            {
                float nm = sqrtf(g0.x*g0.x + g1.x*g1.x);
                float rd = 1.0f / (1.0f + tw * nm);
                q0.x = (p0_cur.x - TAU*g0.x) * rd; q1.x = (p1_cur.x - TAU*g1.x) * rd;
                ln += nm; ld += dt_cur.x * dt_cur.x;
            }
            {
                float nm = sqrtf(g0.y*g0.y + g1.y*g1.y);
                float rd = 1.0f / (1.0f + tw * nm);
                q0.y = (p0_cur.y - TAU*g0.y) * rd; q1.y = (p1_cur.y - TAU*g1.y) * rd;
                ln += nm; ld += dt_cur.y * dt_cur.y;
            }
            {
                float nm = sqrtf(g0.z*g0.z + g1.z*g1.z);
                float rd = 1.0f / (1.0f + tw * nm);
                q0.z = (p0_cur.z - TAU*g0.z) * rd; q1.z = (p1_cur.z - TAU*g1.z) * rd;
                ln += nm; ld += dt_cur.z * dt_cur.z;
            }
            {
                float nm = sqrtf(g0.w*g0.w + g1.w*g1.w);
                float rd = 1.0f / (1.0f + tw * nm);
                q0.w = (p0_cur.w - TAU*g0.w) * rd; q1.w = (p1_cur.w - TAU*g1.w) * rd;
                ln += nm; ld += dt_cur.w * dt_cur.w;
            }
            Q0[iv] = q0; Q1[iv] = q1;

            if (!lastrow) {
                p0_cur = p0_nx; p1_cur = p1_nx; im_cur = im_nx; dt_cur = dt_nx;
            }
        }
    }

    // ---- deterministic block reduction of {dt^2, norm} ----
    #pragma unroll
    for (int o = 16; o > 0; o >>= 1) {
        ld += __shfl_down_sync(0xffffffffu, ld, o);
        ln += __shfl_down_sync(0xffffffffu, ln, o);
    }
    __shared__ float sd[4], sn[4];
    __shared__ int s_last;
    const int wid = tx >> 5;
    if (lane == 0) { sd[wid] = ld; sn[wid] = ln; }
    __syncthreads();
    if (tx == 0) {
        float a = ((sd[0] + sd[1]) + sd[2]) + sd[3];
        float n = ((sn[0] + sn[1]) + sn[2]) + sn[3];
        g_bsum[b][blockIdx.x][0] = a;
        g_bsum[b][blockIdx.x][1] = n;
        __threadfence();
        int old = atomicAdd(&g_cnt[b], 1);
        s_last = (old == BLOCKS_X - 1) ? 1 : 0;
    }
    __syncthreads();

    // ---- last-arriving block: cross-block reduce + convergence update ----
    if (s_last && tx < 32) {
        float a = g_bsum[b][tx][0] + g_bsum[b][tx + 32][0];
        float n = g_bsum[b][tx][1] + g_bsum[b][tx + 32][1];
        #pragma unroll
        for (int o = 16; o > 0; o >>= 1) {
            a += __shfl_down_sync(0xffffffffu, a, o);
            n += __shfl_down_sync(0xffffffffu, n, o);
        }
        if (tx == 0) {
            float Et    = (a + wgt * n) / (float)PLANE;
            float Einit = (iter == 0) ? Et : g_Einit[b];
            if (iter == 0) g_Einit[b] = Et;
            bool conv = (iter > 0) && (fabsf(g_Eprev[b] - Et) < EPSC * Einit);
            g_Eprev[b]   = Et;
            g_lastbuf[b] = wbuf;
            g_cnt[b]     = 0;
            if (conv) g_done[b] = 1;
        }
    }
}

// ---------------- final output: out = img + div(pt at entry of last iter) ---
#define FTBY 8
__global__ void __launch_bounds__(TBX * FTBY)
tv_final_kernel(const float* __restrict__ img, float* __restrict__ out)
{
    const int b    = blockIdx.y;
    const int r    = blockIdx.x * FTBY + threadIdx.y;
    const int c4   = threadIdx.x * 4;
    const int idx  = r * WW + c4;
    const int i4   = idx >> 2;
    const int lane = threadIdx.x & 31;

    const int buf = 1 - g_lastbuf[b];           // pt at entry of last applied iter
    const float*  __restrict__ P0s = &g_pt[buf][b][0][0];
    const float*  __restrict__ P1s = &g_pt[buf][b][1][0];
    const float4* __restrict__ P0  = (const float4*)P0s;
    const float4* __restrict__ P1  = (const float4*)P1s;

    float4 p0c = __ldcs(&P0[i4]);
    float4 p1c = __ldcs(&P1[i4]);
    float4 p0u = (r > 0) ? __ldcs(&P0[i4 - W4]) : make_float4(0,0,0,0);
    float p1l = __shfl_up_sync(0xffffffffu, p1c.w, 1);
    if (lane == 0) p1l = (c4 > 0) ? __ldcs(&P1s[idx - 1]) : 0.f;

    float4 imc = __ldg(&((const float4*)(img + b * PLANE))[i4]);
    float4 o;
    o.x = imc.x + (-(p0c.x + p1c.x) + p0u.x + p1l);
    o.y = imc.y + (-(p0c.y + p1c.y) + p0u.y + p1c.x);
    o.z = imc.z + (-(p0c.z + p1c.z) + p0u.z + p1c.y);
    o.w = imc.w + (-(p0c.w + p1c.w) + p0u.w + p1c.z);
    ((float4*)out)[b * (PLANE/4) + i4] = o;
}

// ---------------- launch ----------------------------------------------------
extern "C" void kernel_launch(void* const* d_in, const int* in_sizes, int n_in,
                              void* d_out, int out_size)
{
    const float* img = (const float*)d_in[0];   // [8,3,512,512] f32
    const float* wgt = (const float*)d_in[1];   // [8] f32
    float* out = (float*)d_out;

    dim3 block(TBX, 1);                         // 128 threads
    dim3 grid(BLOCKS_X, NIMG);                  // 64 x 24

    tv_init_kernel<<<1, 32>>>();

    tv_iter_kernel<true><<<grid, block>>>(img, wgt, 0, 0, 0);
    for (int it = 1; it < NITER; ++it) {
        int wbuf = it & 1;
        int rbuf = 1 - wbuf;
        tv_iter_kernel<false><<<grid, block>>>(img, wgt, rbuf, wbuf, it);
    }

    dim3 fblock(TBX, FTBY);                     // 128 x 8
    dim3 fgrid(HH / FTBY, NIMG);                // 64 x 24
    tv_final_kernel<<<fgrid, fblock>>>(img, out);
}

// round 4
// speedup vs baseline: 1.8809x; 1.0217x over previous
#include <cuda_runtime.h>
#include <math.h>

#define NIMG 24               // B*C = 8*3
#define HH 512
#define WW 512
#define PLANE (HH*WW)
#define NITER 10
#define EPSC 2e-4f
#define TAU 0.25f
#define TBX 128               // threads per block: one 512-px row strip
#define RPT 8                 // rows per block
#define BLOCKS_X (HH/RPT)     // 64 blocks per image
#define W4 (WW/4)             // 128 float4 per row

// ---------------- scratch state (static device globals) ---------------------
__device__ float g_pt[2][NIMG][2][PLANE];       // double-buffered dual field
__device__ float g_bsum[NIMG][BLOCKS_X][2];     // per-block partials {dt^2, norm}
__device__ int   g_cnt[NIMG];                   // arrival counters
__device__ float g_Einit[NIMG];
__device__ float g_Eprev[NIMG];
__device__ int   g_done[NIMG];
__device__ int   g_lastbuf[NIMG];

__global__ void tv_init_kernel() {
    int i = threadIdx.x;
    if (i < NIMG) {
        g_done[i]    = 0;
        g_Einit[i]   = 0.f;
        g_Eprev[i]   = 0.f;
        g_lastbuf[i] = 0;
        g_cnt[i]     = 0;
    }
}

// ---------------- main iteration kernel --------------------------------------
// Block = 128 threads covering a 512x8 strip (4 px/thread/row, rolling down 8
// rows). __launch_bounds__(128, 11): 11 blocks/SM -> the whole 1536-block grid
// is resident in ONE wave (148*11 = 1628), removing the tail, and raises
// warps/SM from ~29 to ~44. Register diet: carry out=img+dt instead of img and
// dt separately (identical arithmetic/order). Old-pt reads use __ldcs
// (evict-first; lines are dead after this read). Fused deterministic energy
// reduction; last-arriving block per image updates convergence state.
template<bool FIRST>
__global__ void __launch_bounds__(TBX, 11)
tv_iter_kernel(const float* __restrict__ img,
               const float* __restrict__ weight,
               int rbuf, int wbuf, int iter)
{
    const int b = blockIdx.y;
    if (g_done[b]) return;

    const int tx   = threadIdx.x;
    const int lane = tx & 31;
    const int c4   = tx * 4;
    const int r0   = blockIdx.x * RPT;
    const bool haveR = (c4 + 4 < WW);

    const float*  __restrict__ imp = img + b * PLANE;
    const float4* __restrict__ im4 = (const float4*)imp;
    const float*  __restrict__ P0s = &g_pt[rbuf][b][0][0];
    const float*  __restrict__ P1s = &g_pt[rbuf][b][1][0];
    const float4* __restrict__ P0  = (const float4*)P0s;
    const float4* __restrict__ P1  = (const float4*)P1s;
    float4* __restrict__ Q0 = (float4*)&g_pt[wbuf][b][0][0];
    float4* __restrict__ Q1 = (float4*)&g_pt[wbuf][b][1][0];

    const float wgt = __ldg(&weight[b / 3]);
    const float tw  = TAU / wgt;

    const int i40 = r0 * W4 + tx;

    float ld = 0.f, ln = 0.f;

    if (FIRST) {
        // pt == 0: out = img, dt = 0
        float4 im_cur = __ldg(&im4[i40]);
        #pragma unroll
        for (int k = 0; k < RPT; ++k) {
            const int r  = r0 + k;
            const int iv = i40 + k * W4;
            const bool lastrow = (r == HH - 1);
            float4 im_nx = make_float4(0,0,0,0);
            if (!lastrow) im_nx = __ldg(&im4[iv + W4]);

            float4 g0;
            if (!lastrow) {
                g0.x = im_nx.x - im_cur.x; g0.y = im_nx.y - im_cur.y;
                g0.z = im_nx.z - im_cur.z; g0.w = im_nx.w - im_cur.w;
            } else g0 = make_float4(0,0,0,0);

            float imr = __shfl_down_sync(0xffffffffu, im_cur.x, 1);
            if (lane == 31 && haveR) imr = __ldg(&imp[r * WW + c4 + 4]);
            float4 g1;
            g1.x = im_cur.y - im_cur.x;
            g1.y = im_cur.z - im_cur.y;
            g1.z = im_cur.w - im_cur.z;
            g1.w = haveR ? (imr - im_cur.w) : 0.f;

            float4 q0, q1;
            {
                float nm = sqrtf(g0.x*g0.x + g1.x*g1.x);
                float rd = 1.0f / (1.0f + tw * nm);
                q0.x = (-TAU * g0.x) * rd; q1.x = (-TAU * g1.x) * rd; ln += nm;
            }
            {
                float nm = sqrtf(g0.y*g0.y + g1.y*g1.y);
                float rd = 1.0f / (1.0f + tw * nm);
                q0.y = (-TAU * g0.y) * rd; q1.y = (-TAU * g1.y) * rd; ln += nm;
            }
            {
                float nm = sqrtf(g0.z*g0.z + g1.z*g1.z);
                float rd = 1.0f / (1.0f + tw * nm);
                q0.z = (-TAU * g0.z) * rd; q1.z = (-TAU * g1.z) * rd; ln += nm;
            }
            {
                float nm = sqrtf(g0.w*g0.w + g1.w*g1.w);
                float rd = 1.0f / (1.0f + tw * nm);
                q0.w = (-TAU * g0.w) * rd; q1.w = (-TAU * g1.w) * rd; ln += nm;
            }
            Q0[iv] = q0; Q1[iv] = q1;
            im_cur = im_nx;
        }
    } else {
        // rolling prologue: row r0
        float4 p0_cur = __ldcs(&P0[i40]);
        float4 p1_cur = __ldcs(&P1[i40]);
        float4 p0u = make_float4(0,0,0,0);
        if (r0 > 0) p0u = __ldcs(&P0[i40 - W4]);
        float p1l = __shfl_up_sync(0xffffffffu, p1_cur.w, 1);
        if (lane == 0) p1l = (c4 > 0) ? __ldcs(&P1s[r0 * WW + c4 - 1]) : 0.f;

        float4 dt_cur;
        dt_cur.x = -(p0_cur.x + p1_cur.x) + p0u.x + p1l;
        dt_cur.y = -(p0_cur.y + p1_cur.y) + p0u.y + p1_cur.x;
        dt_cur.z = -(p0_cur.z + p1_cur.z) + p0u.z + p1_cur.y;
        dt_cur.w = -(p0_cur.w + p1_cur.w) + p0u.w + p1_cur.z;

        float4 im0 = __ldg(&im4[i40]);
        float4 out_cur;
        out_cur.x = im0.x + dt_cur.x;
        out_cur.y = im0.y + dt_cur.y;
        out_cur.z = im0.z + dt_cur.z;
        out_cur.w = im0.w + dt_cur.w;

        #pragma unroll
        for (int k = 0; k < RPT; ++k) {
            const int r  = r0 + k;
            const int iv = i40 + k * W4;
            const bool lastrow = (r == HH - 1);

            float4 p0_nx, p1_nx, dt_nx, out_nx;
            if (!lastrow) {
                p0_nx = __ldcs(&P0[iv + W4]);
                p1_nx = __ldcs(&P1[iv + W4]);
                float4 im_nx = __ldg(&im4[iv + W4]);
                float p1ln = __shfl_up_sync(0xffffffffu, p1_nx.w, 1);
                if (lane == 0)
                    p1ln = (c4 > 0) ? __ldcs(&P1s[(r + 1) * WW + c4 - 1]) : 0.f;
                dt_nx.x = -(p0_nx.x + p1_nx.x) + p0_cur.x + p1ln;
                dt_nx.y = -(p0_nx.y + p1_nx.y) + p0_cur.y + p1_nx.x;
                dt_nx.z = -(p0_nx.z + p1_nx.z) + p0_cur.z + p1_nx.y;
                dt_nx.w = -(p0_nx.w + p1_nx.w) + p0_cur.w + p1_nx.z;
                out_nx.x = im_nx.x + dt_nx.x;
                out_nx.y = im_nx.y + dt_nx.y;
                out_nx.z = im_nx.z + dt_nx.z;
                out_nx.w = im_nx.w + dt_nx.w;
            }

            float4 g0;
            if (!lastrow) {
                g0.x = out_nx.x - out_cur.x;
                g0.y = out_nx.y - out_cur.y;
                g0.z = out_nx.z - out_cur.z;
                g0.w = out_nx.w - out_cur.w;
            } else g0 = make_float4(0,0,0,0);

            float orr = __shfl_down_sync(0xffffffffu, out_cur.x, 1);
            if (lane == 31 && haveR) {
                float q0s = __ldcs(&P0s[r * WW + c4 + 4]);
                float q1s = __ldcs(&P1s[r * WW + c4 + 4]);
                float qus = (r > 0) ? __ldcs(&P0s[(r - 1) * WW + c4 + 4]) : 0.f;
                float dtr = -(q0s + q1s) + qus + p1_cur.w;
                orr = __ldg(&imp[r * WW + c4 + 4]) + dtr;
            }
            float4 g1;
            g1.x = out_cur.y - out_cur.x;
            g1.y = out_cur.z - out_cur.y;
            g1.z = out_cur.w - out_cur.z;
            g1.w = haveR ? (orr - out_cur.w) : 0.f;

            float4 q0, q1;
            {
                float nm = sqrtf(g0.x*g0.x + g1.x*g1.x);
                float rd = 1.0f / (1.0f + tw * nm);
                q0.x = (p0_cur.x - TAU*g0.x) * rd; q1.x = (p1_cur.x - TAU*g1.x) * rd;
                ln += nm; ld += dt_cur.x * dt_cur.x;
            }
            {
                float nm = sqrtf(g0.y*g0.y + g1.y*g1.y);
                float rd = 1.0f / (1.0f + tw * nm);
                q0.y = (p0_cur.y - TAU*g0.y) * rd; q1.y = (p1_cur.y - TAU*g1.y) * rd;
                ln += nm; ld += dt_cur.y * dt_cur.y;
            }
            {
                float nm = sqrtf(g0.z*g0.z + g1.z*g1.z);
                float rd = 1.0f / (1.0f + tw * nm);
                q0.z = (p0_cur.z - TAU*g0.z) * rd; q1.z = (p1_cur.z - TAU*g1.z) * rd;
                ln += nm; ld += dt_cur.z * dt_cur.z;
            }
            {
                float nm = sqrtf(g0.w*g0.w + g1.w*g1.w);
                float rd = 1.0f / (1.0f + tw * nm);
                q0.w = (p0_cur.w - TAU*g0.w) * rd; q1.w = (p1_cur.w - TAU*g1.w) * rd;
                ln += nm; ld += dt_cur.w * dt_cur.w;
            }
            Q0[iv] = q0; Q1[iv] = q1;

            if (!lastrow) {
                p0_cur = p0_nx; p1_cur = p1_nx; out_cur = out_nx; dt_cur = dt_nx;
            }
        }
    }

    // ---- deterministic block reduction of {dt^2, norm} ----
    #pragma unroll
    for (int o = 16; o > 0; o >>= 1) {
        ld += __shfl_down_sync(0xffffffffu, ld, o);
        ln += __shfl_down_sync(0xffffffffu, ln, o);
    }
    __shared__ float sd[4], sn[4];
    __shared__ int s_last;
    const int wid = tx >> 5;
    if (lane == 0) { sd[wid] = ld; sn[wid] = ln; }
    __syncthreads();
    if (tx == 0) {
        float a = ((sd[0] + sd[1]) + sd[2]) + sd[3];
        float n = ((sn[0] + sn[1]) + sn[2]) + sn[3];
        g_bsum[b][blockIdx.x][0] = a;
        g_bsum[b][blockIdx.x][1] = n;
        __threadfence();
        int old = atomicAdd(&g_cnt[b], 1);
        s_last = (old == BLOCKS_X - 1) ? 1 : 0;
    }
    __syncthreads();

    // ---- last-arriving block: cross-block reduce + convergence update ----
    if (s_last && tx < 32) {
        float a = g_bsum[b][tx][0] + g_bsum[b][tx + 32][0];
        float n = g_bsum[b][tx][1] + g_bsum[b][tx + 32][1];
        #pragma unroll
        for (int o = 16; o > 0; o >>= 1) {
            a += __shfl_down_sync(0xffffffffu, a, o);
            n += __shfl_down_sync(0xffffffffu, n, o);
        }
        if (tx == 0) {
            float Et    = (a + wgt * n) / (float)PLANE;
            float Einit = (iter == 0) ? Et : g_Einit[b];
            if (iter == 0) g_Einit[b] = Et;
            bool conv = (iter > 0) && (fabsf(g_Eprev[b] - Et) < EPSC * Einit);
            g_Eprev[b]   = Et;
            g_lastbuf[b] = wbuf;
            g_cnt[b]     = 0;
            if (conv) g_done[b] = 1;
        }
    }
}

// ---------------- final output: out = img + div(pt at entry of last iter) ---
#define FTBY 8
__global__ void __launch_bounds__(TBX * FTBY)
tv_final_kernel(const float* __restrict__ img, float* __restrict__ out)
{
    const int b    = blockIdx.y;
    const int r    = blockIdx.x * FTBY + threadIdx.y;
    const int c4   = threadIdx.x * 4;
    const int idx  = r * WW + c4;
    const int i4   = idx >> 2;
    const int lane = threadIdx.x & 31;

    const int buf = 1 - g_lastbuf[b];           // pt at entry of last applied iter
    const float*  __restrict__ P0s = &g_pt[buf][b][0][0];
    const float*  __restrict__ P1s = &g_pt[buf][b][1][0];
    const float4* __restrict__ P0  = (const float4*)P0s;
    const float4* __restrict__ P1  = (const float4*)P1s;

    float4 p0c = __ldcs(&P0[i4]);
    float4 p1c = __ldcs(&P1[i4]);
    float4 p0u = (r > 0) ? __ldcs(&P0[i4 - W4]) : make_float4(0,0,0,0);
    float p1l = __shfl_up_sync(0xffffffffu, p1c.w, 1);
    if (lane == 0) p1l = (c4 > 0) ? __ldcs(&P1s[idx - 1]) : 0.f;

    float4 imc = __ldg(&((const float4*)(img + b * PLANE))[i4]);
    float4 o;
    o.x = imc.x + (-(p0c.x + p1c.x) + p0u.x + p1l);
    o.y = imc.y + (-(p0c.y + p1c.y) + p0u.y + p1c.x);
    o.z = imc.z + (-(p0c.z + p1c.z) + p0u.z + p1c.y);
    o.w = imc.w + (-(p0c.w + p1c.w) + p0u.w + p1c.z);
    ((float4*)out)[b * (PLANE/4) + i4] = o;
}

// ---------------- launch ----------------------------------------------------
extern "C" void kernel_launch(void* const* d_in, const int* in_sizes, int n_in,
                              void* d_out, int out_size)
{
    const float* img = (const float*)d_in[0];   // [8,3,512,512] f32
    const float* wgt = (const float*)d_in[1];   // [8] f32
    float* out = (float*)d_out;

    dim3 block(TBX, 1);                         // 128 threads
    dim3 grid(BLOCKS_X, NIMG);                  // 64 x 24

    tv_init_kernel<<<1, 32>>>();

    tv_iter_kernel<true><<<grid, block>>>(img, wgt, 0, 0, 0);
    for (int it = 1; it < NITER; ++it) {
        int wbuf = it & 1;
        int rbuf = 1 - wbuf;
        tv_iter_kernel<false><<<grid, block>>>(img, wgt, rbuf, wbuf, it);
    }

    dim3 fblock(TBX, FTBY);                     // 128 x 8
    dim3 fgrid(HH / FTBY, NIMG);                // 64 x 24
    tv_final_kernel<<<fgrid, fblock>>>(img, out);
}